// round 13
// baseline (speedup 1.0000x reference)
#include <cuda_runtime.h>
#include <cstdint>

#define BB   16
#define HH   64
#define WW   64
#define CC   512
#define RR   256
#define NSEL 64
#define PHW  7
#define POOLED_ELEMS (BB * NSEL * PHW * PHW * CC)  // 25,690,112
#define NMS_CTAS (BB * 8)
#define POOL_CTAS (BB * NSEL * 4)

__device__ int4 g_roiclip[BB * NSEL];
__device__ int  g_order[BB * NSEL];                    // batch-major, big-first within batch
__device__ unsigned long long g_mask[BB * RR * 4];     // upper-triangle suppression masks
__device__ int  g_cnt[BB];                             // mask-CTA arrival counter (self-reset)
__device__ int  g_ready[BB];                           // batch-b results published
__device__ int  g_done[BB];                            // pool-CTA completion counter (self-reset)

__device__ __forceinline__ void fix_axis(int& mn, int& mx, int ps, int fs) {
    int pad = ps - (mx - mn);
    if (pad > 0) {
        if (mn < (pad >> 1))                { mn = 0;       mx = ps; }
        else if (fs - mx < ((1 + pad) >> 1)){ mn = fs - ps; mx = fs; }
        else { mn -= (pad >> 1); mx += (1 + pad) >> 1; }
    }
}

__device__ __forceinline__ float4 f4max(float4 a, float4 b) {
    return make_float4(fmaxf(a.x, b.x), fmaxf(a.y, b.y),
                       fmaxf(a.z, b.z), fmaxf(a.w, b.w));
}

// ---- NMS role: masks; the LAST CTA of each batch resolves + clips + ranks + publishes ----
__device__ void nms_role(int bi, const float* __restrict__ roi,
                         float* __restrict__ out, int write_tail) {
    __shared__ float4 sbox[RR];   // x1, y1, x2, y2
    __shared__ float  sarea[RR];
    __shared__ int s_last;

    const int b = bi >> 3;
    const int q = bi & 7;         // 32-wide j chunk, 0..7
    const int t = threadIdx.x;

    const float4 rv = ((const float4*)roi)[b * RR + t];
    const float x1 = rv.x, y1 = rv.y;
    const float x2 = rv.x + rv.z, y2 = rv.y + rv.w;
    const float area = (y2 - y1) * (x2 - x1);
    sbox[t]  = make_float4(x1, y1, x2, y2);
    sarea[t] = area;
    __syncthreads();

    unsigned mg = 0u;
    const int j0 = max(q * 32, t + 1);
    const int j1 = q * 32 + 32;
#pragma unroll 2
    for (int j = j0; j < j1; ++j) {
        const float4 o = sbox[j];
        const float ih = fmaxf(fminf(y2, o.w) - fmaxf(y1, o.y), 0.0f);
        const float iw = fmaxf(fminf(x2, o.z) - fmaxf(x1, o.x), 0.0f);
        const float inter = ih * iw;
        // inter == 0  =>  reference IoU is exactly 0 (no divide needed).
        // inter > 0   =>  union >= max(area) > 0, so the where() guard is satisfied.
        if (inter > 0.0f) {
            const float uni = area + sarea[j] - inter;
            // exact IEEE divide so the >0.4 decision matches JAX bit-for-bit
            const float iou = __fdiv_rn(inter, uni);
            if (iou > 0.4f) mg |= 1u << (j & 31);
        }
    }
    // u32 alias of the u64 mask array: word q covers bits [32q, 32q+32) (little-endian)
    ((unsigned*)g_mask)[(b * RR + t) * 8 + q] = mg;

    // Publish + count. Only the 8th (last) CTA of this batch continues to resolve.
    __threadfence();
    __syncthreads();
    if (t == 0) s_last = (atomicAdd(&g_cnt[b], 1) == 7) ? 1 : 0;
    __syncthreads();
    if (!s_last) return;
    __threadfence();                 // acquire: all 8 CTAs' mask writes now visible

    // ---- resolve phase (one CTA per batch) ----
    __shared__ unsigned long long sm[RR][4];
    __shared__ int sidx[NSEL];
    __shared__ int sarea_i[NSEL];

    const unsigned long long* gm = g_mask + (size_t)b * RR * 4;
    for (int idx = t; idx < RR * 4; idx += RR)
        ((unsigned long long*)sm)[idx] = gm[idx];
    __syncthreads();

    if (t == 0) {
        g_cnt[b] = 0;                // reset for the next graph replay
        int n = 0;
        unsigned long long alive1 = ~0ull, alive2 = ~0ull, alive3 = ~0ull;
        {
            unsigned long long a = ~0ull;
            while (a && n < NSEL) {
                const int k = __ffsll((long long)a) - 1;
                sidx[n++] = k;
                a &= ~((1ull << k) | sm[k][0]);
                alive1 &= ~sm[k][1]; alive2 &= ~sm[k][2]; alive3 &= ~sm[k][3];
            }
        }
        if (n < NSEL) {
            unsigned long long a = alive1;
            while (a && n < NSEL) {
                const int k = __ffsll((long long)a) - 1;
                const int i = 64 + k;
                sidx[n++] = i;
                a &= ~((1ull << k) | sm[i][1]);
                alive2 &= ~sm[i][2]; alive3 &= ~sm[i][3];
            }
        }
        if (n < NSEL) {
            unsigned long long a = alive2;
            while (a && n < NSEL) {
                const int k = __ffsll((long long)a) - 1;
                const int i = 128 + k;
                sidx[n++] = i;
                a &= ~((1ull << k) | sm[i][2]);
                alive3 &= ~sm[i][3];
            }
        }
        if (n < NSEL) {
            unsigned long long a = alive3;
            while (a && n < NSEL) {
                const int k = __ffsll((long long)a) - 1;
                const int i = 192 + k;
                sidx[n++] = i;
                a &= ~((1ull << k) | sm[i][3]);
            }
        }
        for (int q2 = n; q2 < NSEL; ++q2) sidx[q2] = RR - NSEL + q2;  // fill = 192 + q
    }
    __syncthreads();

    // Clip the 64 selected ROIs, publish for the pool CTAs, emit tail output.
    if (t < NSEL) {
        const float4 rr = ((const float4*)roi)[b * RR + sidx[t]];
        int xmin = (int)fmaxf(0.0f, rr.x);
        int ymin = (int)fmaxf(0.0f, rr.y);
        int xmax = (int)fminf((float)WW, rr.x + rr.z);
        int ymax = (int)fminf((float)HH, rr.y + rr.w);
        fix_axis(xmin, xmax, PHW, WW);
        fix_axis(ymin, ymax, PHW, HH);
        int4 rc;
        rc.x = xmin; rc.y = ymin; rc.z = xmax - xmin; rc.w = ymax - ymin;
        g_roiclip[b * NSEL + t] = rc;
        sarea_i[t] = rc.z * rc.w;
        if (write_tail) {
            float* tp = out + (size_t)POOLED_ELEMS + (size_t)(b * NSEL + t) * 4;
            tp[0] = (float)rc.x; tp[1] = (float)rc.y;
            tp[2] = (float)rc.z; tp[3] = (float)rc.w;
        }
    }
    __syncthreads();

    // Rank by area desc (batch-major big-first), then publish the ready flag.
    if (t < NSEL) {
        const int a = sarea_i[t];
        int rank = 0;
#pragma unroll 8
        for (int j = 0; j < NSEL; ++j) {
            const int aj = sarea_i[j];
            rank += (aj > a) || (aj == a && j < t);
        }
        g_order[b * NSEL + rank] = b * NSEL + t;
    }
    __syncthreads();
    if (t == 0) {
        __threadfence();             // release: order/roiclip visible before flag
        atomicExch(&g_ready[b], 1);
    }
}

// ---- Pool role: waits for its batch, then pools. 8 groups x 32 float4-lanes ----
__device__ void pool_role(int idx, const float* __restrict__ feat, float* __restrict__ out) {
    const int b = idx >> 8;                      // batch known before g_order (batch-major)

    // Wait for batch b's NMS results. Only NMS CTAs (earlier in the grid) produce
    // the flag, and they never wait -> no deadlock.
    if (threadIdx.x == 0) {
        while (atomicAdd(&g_ready[b], 0) == 0) __nanosleep(64);
    }
    __syncthreads();
    __threadfence();                              // acquire

    const int slot = g_order[idx >> 2];
    const int quarter = idx & 3;
    const int4 rc = g_roiclip[slot];
    const int x = rc.x, y = rc.y, w = rc.z, h = rc.w;
    const int lane = threadIdx.x & 31;
    const int g    = threadIdx.x >> 5;           // group 0..7
    const int t    = quarter * 32 + lane;        // float4 lane in [0,128)
    const int CV   = CC / 4;                     // 128 float4 per position

    const float4* __restrict__ fm = (const float4*)feat + (size_t)b * HH * WW * CV;
    float4* __restrict__ o = (float4*)out + (size_t)slot * (PHW * PHW) * CV;

    const float NEGF = -__int_as_float(0x7f800000);
    const float4 NEG4 = make_float4(NEGF, NEGF, NEGF, NEGF);

    // ---- 6x6 direct copy: 36 positions; groups 0-7 take 4 each, groups 0-3 one extra ----
#pragma unroll
    for (int k = 0; k < 4; ++k) {
        const int p = g * 4 + k;
        const int i = p / 6, j = p - 6 * i;
        __stcs(&o[(i * 7 + j) * CV + t], fm[((y + i) * WW + (x + j)) * CV + t]);
    }
    if (g < 4) {
        const int p = 32 + g;
        const int i = p / 6, j = p - 6 * i;
        __stcs(&o[(i * 7 + j) * CV + t], fm[((y + i) * WW + (x + j)) * CV + t]);
    }

    // ---- strips: 12 tasks (0-5 col-strip rows, 6-11 row-strip cols) over 8 groups ----
#pragma unroll
    for (int rep = 0; rep < 2; ++rep) {
        const int s = rep == 0 ? g : (g < 4 ? 8 + g : 12);
        if (s < 6) {
            const int i = s;
            float4 a0 = NEG4, a1 = NEG4, a2 = NEG4, a3 = NEG4;
            const float4* row = fm + (size_t)(y + i) * WW * CV;
            int jj = x + 6;
            for (; jj + 3 < x + w; jj += 4) {
                a0 = f4max(a0, row[(jj    ) * CV + t]);
                a1 = f4max(a1, row[(jj + 1) * CV + t]);
                a2 = f4max(a2, row[(jj + 2) * CV + t]);
                a3 = f4max(a3, row[(jj + 3) * CV + t]);
            }
            for (; jj < x + w; ++jj) a0 = f4max(a0, row[jj * CV + t]);
            __stcs(&o[(i * 7 + 6) * CV + t], f4max(f4max(a0, a1), f4max(a2, a3)));
        } else if (s < 12) {
            const int j = s - 6;
            float4 a0 = NEG4, a1 = NEG4, a2 = NEG4, a3 = NEG4;
            const float4* col = fm + (size_t)(x + j) * CV;
            int ii = y + 6;
            for (; ii + 3 < y + h; ii += 4) {
                a0 = f4max(a0, col[(ii    ) * WW * CV + t]);
                a1 = f4max(a1, col[(ii + 1) * WW * CV + t]);
                a2 = f4max(a2, col[(ii + 2) * WW * CV + t]);
                a3 = f4max(a3, col[(ii + 3) * WW * CV + t]);
            }
            for (; ii < y + h; ++ii) a0 = f4max(a0, col[ii * WW * CV + t]);
            __stcs(&o[(42 + j) * CV + t], f4max(f4max(a0, a1), f4max(a2, a3)));
        }
    }

    // ---- corner: rows interleaved x8 across groups, smem combine ----
    {
        __shared__ float4 sbuf[7][32];
        float4 a0 = NEG4, a1 = NEG4, a2 = NEG4, a3 = NEG4;
        for (int ii = y + 6 + g; ii < y + h; ii += 8) {
            const float4* row = fm + (size_t)ii * WW * CV;
            int jj = x + 6;
            for (; jj + 3 < x + w; jj += 4) {
                a0 = f4max(a0, row[(jj    ) * CV + t]);
                a1 = f4max(a1, row[(jj + 1) * CV + t]);
                a2 = f4max(a2, row[(jj + 2) * CV + t]);
                a3 = f4max(a3, row[(jj + 3) * CV + t]);
            }
            for (; jj < x + w; ++jj) a0 = f4max(a0, row[jj * CV + t]);
        }
        float4 a = f4max(f4max(a0, a1), f4max(a2, a3));
        if (g > 0) sbuf[g - 1][lane] = a;
        __syncthreads();
        if (g == 0) {
            float4 m01 = f4max(sbuf[0][lane], sbuf[1][lane]);
            float4 m23 = f4max(sbuf[2][lane], sbuf[3][lane]);
            float4 m45 = f4max(sbuf[4][lane], sbuf[5][lane]);
            a = f4max(f4max(a, sbuf[6][lane]), f4max(f4max(m01, m23), m45));
            __stcs(&o[48 * CV + t], a);
        }
    }

    // Self-reset: the last pool CTA of batch b clears the flags for graph replay.
    __syncthreads();
    if (threadIdx.x == 0) {
        if (atomicAdd(&g_done[b], 1) == 255) {   // 64 ROIs x 4 quarters = 256 CTAs
            g_done[b]  = 0;
            g_ready[b] = 0;
        }
    }
}

__global__ __launch_bounds__(256)
void fused_kernel(const float* __restrict__ feat, const float* __restrict__ roi,
                  float* __restrict__ out, int write_tail) {
    const int bi = blockIdx.x;
    if (bi < NMS_CTAS) nms_role(bi, roi, out, write_tail);
    else               pool_role(bi - NMS_CTAS, feat, out);
}

extern "C" void kernel_launch(void* const* d_in, const int* in_sizes, int n_in,
                              void* d_out, int out_size) {
    const float* feat = (const float*)d_in[0];
    const float* roi  = (const float*)d_in[1];
    // defensive: identify inputs by size (features = 33,554,432; roi = 16,384)
    if (n_in >= 2 && in_sizes[0] == BB * RR * 4) {
        feat = (const float*)d_in[1];
        roi  = (const float*)d_in[0];
    }
    float* out = (float*)d_out;
    const int write_tail = (out_size >= POOLED_ELEMS + BB * NSEL * 4) ? 1 : 0;

    fused_kernel<<<NMS_CTAS + POOL_CTAS, 256>>>(feat, roi, out, write_tail);
}

// round 14
// speedup vs baseline: 1.0066x; 1.0066x over previous
#include <cuda_runtime.h>
#include <cstdint>

#define BB   16
#define HH   64
#define WW   64
#define CC   512
#define RR   256
#define NSEL 64
#define PHW  7
#define POOLED_ELEMS (BB * NSEL * PHW * PHW * CC)  // 25,690,112

__device__ int4 g_roiclip[BB * NSEL];
__device__ int  g_order[BB * NSEL];                    // batch-major, big-first within batch
__device__ unsigned long long g_mask[BB * RR * 4];     // upper-triangle suppression masks
__device__ int  g_cnt[BB];                             // zero-init; self-resetting per launch

__device__ __forceinline__ void fix_axis(int& mn, int& mx, int ps, int fs) {
    int pad = ps - (mx - mn);
    if (pad > 0) {
        if (mn < (pad >> 1))                { mn = 0;       mx = ps; }
        else if (fs - mx < ((1 + pad) >> 1)){ mn = fs - ps; mx = fs; }
        else { mn -= (pad >> 1); mx += (1 + pad) >> 1; }
    }
}

// ---- Stage 1 (fused): masks over 16-wide chunks (256 CTAs); the LAST CTA of each
//      batch resolves + clips + ranks ----
__global__ __launch_bounds__(RR)
void nms_kernel(const float* __restrict__ roi, float* __restrict__ out, int write_tail) {
    __shared__ float4 sbox[RR];   // x1, y1, x2, y2
    __shared__ float  sarea[RR];
    __shared__ int s_last;

    const int b = blockIdx.x;
    const int q = blockIdx.y;     // 16-wide j chunk, 0..15
    const int t = threadIdx.x;

    const float4 rv = ((const float4*)roi)[b * RR + t];
    const float x1 = rv.x, y1 = rv.y;
    const float x2 = rv.x + rv.z, y2 = rv.y + rv.w;
    const float area = (y2 - y1) * (x2 - x1);
    sbox[t]  = make_float4(x1, y1, x2, y2);
    sarea[t] = area;
    __syncthreads();

    unsigned mg = 0u;
    const int j0 = max(q * 16, t + 1);
    const int j1 = q * 16 + 16;
    for (int j = j0; j < j1; ++j) {
        const float4 o = sbox[j];
        const float ih = fmaxf(fminf(y2, o.w) - fmaxf(y1, o.y), 0.0f);
        const float iw = fmaxf(fminf(x2, o.z) - fmaxf(x1, o.x), 0.0f);
        const float inter = ih * iw;
        // inter == 0  =>  reference IoU is exactly 0 (no divide needed).
        // inter > 0   =>  union >= max(area) > 0, so the where() guard is satisfied.
        if (inter > 0.0f) {
            const float uni = area + sarea[j] - inter;
            // exact IEEE divide so the >0.4 decision matches JAX bit-for-bit
            const float iou = __fdiv_rn(inter, uni);
            if (iou > 0.4f) mg |= 1u << (j & 15);
        }
    }
    // u16 alias of the u64 mask array: word q covers bits [16q, 16q+16) (little-endian)
    ((unsigned short*)g_mask)[(b * RR + t) * 16 + q] = (unsigned short)mg;

    // Publish + count. Only the 16th (last) CTA of this batch continues to resolve.
    __threadfence();
    __syncthreads();
    if (t == 0) s_last = (atomicAdd(&g_cnt[b], 1) == 15) ? 1 : 0;
    __syncthreads();
    if (!s_last) return;
    __threadfence();                 // acquire: all 16 CTAs' mask writes now visible

    // ---- resolve phase (one CTA per batch) ----
    __shared__ unsigned long long sm[RR][4];
    __shared__ int sidx[NSEL];
    __shared__ int sarea_i[NSEL];

    const unsigned long long* gm = g_mask + (size_t)b * RR * 4;
    for (int idx = t; idx < RR * 4; idx += RR)
        ((unsigned long long*)sm)[idx] = gm[idx];
    __syncthreads();

    if (t == 0) {
        g_cnt[b] = 0;                // reset for the next graph replay
        int n = 0;
        unsigned long long alive1 = ~0ull, alive2 = ~0ull, alive3 = ~0ull;
        {
            unsigned long long a = ~0ull;
            while (a && n < NSEL) {
                const int k = __ffsll((long long)a) - 1;
                sidx[n++] = k;
                a &= ~((1ull << k) | sm[k][0]);
                alive1 &= ~sm[k][1]; alive2 &= ~sm[k][2]; alive3 &= ~sm[k][3];
            }
        }
        if (n < NSEL) {
            unsigned long long a = alive1;
            while (a && n < NSEL) {
                const int k = __ffsll((long long)a) - 1;
                const int i = 64 + k;
                sidx[n++] = i;
                a &= ~((1ull << k) | sm[i][1]);
                alive2 &= ~sm[i][2]; alive3 &= ~sm[i][3];
            }
        }
        if (n < NSEL) {
            unsigned long long a = alive2;
            while (a && n < NSEL) {
                const int k = __ffsll((long long)a) - 1;
                const int i = 128 + k;
                sidx[n++] = i;
                a &= ~((1ull << k) | sm[i][2]);
                alive3 &= ~sm[i][3];
            }
        }
        if (n < NSEL) {
            unsigned long long a = alive3;
            while (a && n < NSEL) {
                const int k = __ffsll((long long)a) - 1;
                const int i = 192 + k;
                sidx[n++] = i;
                a &= ~((1ull << k) | sm[i][3]);
            }
        }
        for (int q2 = n; q2 < NSEL; ++q2) sidx[q2] = RR - NSEL + q2;  // fill = 192 + q
    }
    __syncthreads();

    // Clip the 64 selected ROIs, publish for the pooling kernel, emit tail output.
    if (t < NSEL) {
        const float4 rr = ((const float4*)roi)[b * RR + sidx[t]];
        int xmin = (int)fmaxf(0.0f, rr.x);
        int ymin = (int)fmaxf(0.0f, rr.y);
        int xmax = (int)fminf((float)WW, rr.x + rr.z);
        int ymax = (int)fminf((float)HH, rr.y + rr.w);
        fix_axis(xmin, xmax, PHW, WW);
        fix_axis(ymin, ymax, PHW, HH);
        int4 rc;
        rc.x = xmin; rc.y = ymin; rc.z = xmax - xmin; rc.w = ymax - ymin;
        g_roiclip[b * NSEL + t] = rc;
        sarea_i[t] = rc.z * rc.w;
        if (write_tail) {
            float* tp = out + (size_t)POOLED_ELEMS + (size_t)(b * NSEL + t) * 4;
            tp[0] = (float)rc.x; tp[1] = (float)rc.y;
            tp[2] = (float)rc.z; tp[3] = (float)rc.w;
        }
    }
    __syncthreads();

    // Rank by area desc. Batch-major order keeps concurrent CTAs within ~2 batches
    // so the feature working set stays L2-resident.
    if (t < NSEL) {
        const int a = sarea_i[t];
        int rank = 0;
#pragma unroll 8
        for (int j = 0; j < NSEL; ++j) {
            const int aj = sarea_i[j];
            rank += (aj > a) || (aj == a && j < t);
        }
        g_order[b * NSEL + rank] = b * NSEL + t;
    }
}

__device__ __forceinline__ float4 f4max(float4 a, float4 b) {
    return make_float4(fmaxf(a.x, b.x), fmaxf(a.y, b.y),
                       fmaxf(a.z, b.z), fmaxf(a.w, b.w));
}

// ---- Stage 2: pooling. grid = 4096 (ROI x channel-quarter), 8 groups x 32 float4-lanes ----
// R12 config + minBlocksPerMultiprocessor=5 (51-reg cap; mild squeeze from 54).
__global__ __launch_bounds__(256, 5)
void pool_kernel(const float* __restrict__ feat, float* __restrict__ out) {
    const int slot = g_order[blockIdx.x >> 2];
    const int quarter = blockIdx.x & 3;
    const int b  = slot >> 6;
    const int4 rc = g_roiclip[slot];
    const int x = rc.x, y = rc.y, w = rc.z, h = rc.w;
    const int lane = threadIdx.x & 31;
    const int g    = threadIdx.x >> 5;           // group 0..7
    const int t    = quarter * 32 + lane;        // float4 lane in [0,128)
    const int CV   = CC / 4;                     // 128 float4 per position

    const float4* __restrict__ fm = (const float4*)feat + (size_t)b * HH * WW * CV;
    float4* __restrict__ o = (float4*)out + (size_t)slot * (PHW * PHW) * CV;

    const float NEGF = -__int_as_float(0x7f800000);
    const float4 NEG4 = make_float4(NEGF, NEGF, NEGF, NEGF);

    // ---- 6x6 direct copy: 36 positions; groups 0-7 take 4 each, groups 0-3 one extra ----
#pragma unroll
    for (int k = 0; k < 4; ++k) {
        const int p = g * 4 + k;
        const int i = p / 6, j = p - 6 * i;
        __stcs(&o[(i * 7 + j) * CV + t], fm[((y + i) * WW + (x + j)) * CV + t]);
    }
    if (g < 4) {
        const int p = 32 + g;
        const int i = p / 6, j = p - 6 * i;
        __stcs(&o[(i * 7 + j) * CV + t], fm[((y + i) * WW + (x + j)) * CV + t]);
    }

    // ---- strips: 12 tasks (0-5 col-strip rows, 6-11 row-strip cols) over 8 groups ----
#pragma unroll
    for (int rep = 0; rep < 2; ++rep) {
        const int s = rep == 0 ? g : (g < 4 ? 8 + g : 12);
        if (s < 6) {
            const int i = s;
            float4 a0 = NEG4, a1 = NEG4, a2 = NEG4, a3 = NEG4;
            const float4* row = fm + (size_t)(y + i) * WW * CV;
            int jj = x + 6;
            for (; jj + 3 < x + w; jj += 4) {
                a0 = f4max(a0, row[(jj    ) * CV + t]);
                a1 = f4max(a1, row[(jj + 1) * CV + t]);
                a2 = f4max(a2, row[(jj + 2) * CV + t]);
                a3 = f4max(a3, row[(jj + 3) * CV + t]);
            }
            for (; jj < x + w; ++jj) a0 = f4max(a0, row[jj * CV + t]);
            __stcs(&o[(i * 7 + 6) * CV + t], f4max(f4max(a0, a1), f4max(a2, a3)));
        } else if (s < 12) {
            const int j = s - 6;
            float4 a0 = NEG4, a1 = NEG4, a2 = NEG4, a3 = NEG4;
            const float4* col = fm + (size_t)(x + j) * CV;
            int ii = y + 6;
            for (; ii + 3 < y + h; ii += 4) {
                a0 = f4max(a0, col[(ii    ) * WW * CV + t]);
                a1 = f4max(a1, col[(ii + 1) * WW * CV + t]);
                a2 = f4max(a2, col[(ii + 2) * WW * CV + t]);
                a3 = f4max(a3, col[(ii + 3) * WW * CV + t]);
            }
            for (; ii < y + h; ++ii) a0 = f4max(a0, col[ii * WW * CV + t]);
            __stcs(&o[(42 + j) * CV + t], f4max(f4max(a0, a1), f4max(a2, a3)));
        }
    }

    // ---- corner: rows interleaved x8 across groups, smem combine ----
    {
        __shared__ float4 sbuf[7][32];
        float4 a0 = NEG4, a1 = NEG4, a2 = NEG4, a3 = NEG4;
        for (int ii = y + 6 + g; ii < y + h; ii += 8) {
            const float4* row = fm + (size_t)ii * WW * CV;
            int jj = x + 6;
            for (; jj + 3 < x + w; jj += 4) {
                a0 = f4max(a0, row[(jj    ) * CV + t]);
                a1 = f4max(a1, row[(jj + 1) * CV + t]);
                a2 = f4max(a2, row[(jj + 2) * CV + t]);
                a3 = f4max(a3, row[(jj + 3) * CV + t]);
            }
            for (; jj < x + w; ++jj) a0 = f4max(a0, row[jj * CV + t]);
        }
        float4 a = f4max(f4max(a0, a1), f4max(a2, a3));
        if (g > 0) sbuf[g - 1][lane] = a;
        __syncthreads();
        if (g == 0) {
            float4 m01 = f4max(sbuf[0][lane], sbuf[1][lane]);
            float4 m23 = f4max(sbuf[2][lane], sbuf[3][lane]);
            float4 m45 = f4max(sbuf[4][lane], sbuf[5][lane]);
            a = f4max(f4max(a, sbuf[6][lane]), f4max(f4max(m01, m23), m45));
            __stcs(&o[48 * CV + t], a);
        }
    }
}

extern "C" void kernel_launch(void* const* d_in, const int* in_sizes, int n_in,
                              void* d_out, int out_size) {
    const float* feat = (const float*)d_in[0];
    const float* roi  = (const float*)d_in[1];
    // defensive: identify inputs by size (features = 33,554,432; roi = 16,384)
    if (n_in >= 2 && in_sizes[0] == BB * RR * 4) {
        feat = (const float*)d_in[1];
        roi  = (const float*)d_in[0];
    }
    float* out = (float*)d_out;
    const int write_tail = (out_size >= POOLED_ELEMS + BB * NSEL * 4) ? 1 : 0;

    nms_kernel<<<dim3(BB, 16), RR>>>(roi, out, write_tail);
    pool_kernel<<<BB * NSEL * 4, 256>>>(feat, out);
}

// round 15
// speedup vs baseline: 1.0892x; 1.0821x over previous
#include <cuda_runtime.h>
#include <cstdint>

#define BB   16
#define HH   64
#define WW   64
#define CC   512
#define RR   256
#define NSEL 64
#define PHW  7
#define POOLED_ELEMS (BB * NSEL * PHW * PHW * CC)  // 25,690,112

__device__ int4 g_roiclip[BB * NSEL];
__device__ int  g_order[BB * NSEL];                    // batch-major, big-first within batch
__device__ unsigned long long g_mask[BB * RR * 4];     // upper-triangle suppression masks
__device__ int  g_cnt[BB];                             // zero-init; self-resetting per launch

__device__ __forceinline__ void fix_axis(int& mn, int& mx, int ps, int fs) {
    int pad = ps - (mx - mn);
    if (pad > 0) {
        if (mn < (pad >> 1))                { mn = 0;       mx = ps; }
        else if (fs - mx < ((1 + pad) >> 1)){ mn = fs - ps; mx = fs; }
        else { mn -= (pad >> 1); mx += (1 + pad) >> 1; }
    }
}

// ---- Stage 1 (fused): masks over 16-wide chunks (256 CTAs); the LAST CTA of each
//      batch resolves + clips + ranks ----
__global__ __launch_bounds__(RR)
void nms_kernel(const float* __restrict__ roi, float* __restrict__ out, int write_tail) {
    __shared__ float4 sbox[RR];   // x1, y1, x2, y2
    __shared__ float  sarea[RR];
    __shared__ int s_last;

    const int b = blockIdx.x;
    const int q = blockIdx.y;     // 16-wide j chunk, 0..15
    const int t = threadIdx.x;

    const float4 rv = ((const float4*)roi)[b * RR + t];
    const float x1 = rv.x, y1 = rv.y;
    const float x2 = rv.x + rv.z, y2 = rv.y + rv.w;
    const float area = (y2 - y1) * (x2 - x1);
    sbox[t]  = make_float4(x1, y1, x2, y2);
    sarea[t] = area;
    __syncthreads();

    unsigned mg = 0u;
    const int j0 = max(q * 16, t + 1);
    const int j1 = q * 16 + 16;
    for (int j = j0; j < j1; ++j) {
        const float4 o = sbox[j];
        const float ih = fmaxf(fminf(y2, o.w) - fmaxf(y1, o.y), 0.0f);
        const float iw = fmaxf(fminf(x2, o.z) - fmaxf(x1, o.x), 0.0f);
        const float inter = ih * iw;
        // inter == 0  =>  reference IoU is exactly 0 (no divide needed).
        // inter > 0   =>  union >= max(area) > 0, so the where() guard is satisfied.
        if (inter > 0.0f) {
            const float uni = area + sarea[j] - inter;
            // exact IEEE divide so the >0.4 decision matches JAX bit-for-bit
            const float iou = __fdiv_rn(inter, uni);
            if (iou > 0.4f) mg |= 1u << (j & 15);
        }
    }
    // u16 alias of the u64 mask array: word q covers bits [16q, 16q+16) (little-endian)
    ((unsigned short*)g_mask)[(b * RR + t) * 16 + q] = (unsigned short)mg;

    // Publish + count. Only the 16th (last) CTA of this batch continues to resolve.
    __threadfence();
    __syncthreads();
    if (t == 0) s_last = (atomicAdd(&g_cnt[b], 1) == 15) ? 1 : 0;
    __syncthreads();
    if (!s_last) return;
    __threadfence();                 // acquire: all 16 CTAs' mask writes now visible

    // ---- resolve phase (one CTA per batch) ----
    __shared__ ulonglong2 sm[RR][2];             // sm[i] = {w0,w1},{w2,w3}
    __shared__ int sidx[NSEL];
    __shared__ int sarea_i[NSEL];

    const ulonglong2* gm = (const ulonglong2*)(g_mask + (size_t)b * RR * 4);
    for (int idx = t; idx < RR * 2; idx += RR)
        ((ulonglong2*)sm)[idx] = gm[idx];
    __syncthreads();

    if (t == 0) {
        g_cnt[b] = 0;                // reset for the next graph replay
        int n = 0;
        unsigned long long alive1 = ~0ull, alive2 = ~0ull, alive3 = ~0ull;
        {
            unsigned long long a = ~0ull;
            while (a && n < NSEL) {
                const int k = __ffsll((long long)a) - 1;
                sidx[n++] = k;
                const ulonglong2 m01 = sm[k][0];
                const ulonglong2 m23 = sm[k][1];
                a &= ~((1ull << k) | m01.x);
                alive1 &= ~m01.y; alive2 &= ~m23.x; alive3 &= ~m23.y;
            }
        }
        if (n < NSEL) {
            unsigned long long a = alive1;
            while (a && n < NSEL) {
                const int k = __ffsll((long long)a) - 1;
                const int i = 64 + k;
                sidx[n++] = i;
                const ulonglong2 m01 = sm[i][0];
                const ulonglong2 m23 = sm[i][1];
                a &= ~((1ull << k) | m01.y);
                alive2 &= ~m23.x; alive3 &= ~m23.y;
            }
        }
        if (n < NSEL) {
            unsigned long long a = alive2;
            while (a && n < NSEL) {
                const int k = __ffsll((long long)a) - 1;
                const int i = 128 + k;
                sidx[n++] = i;
                const ulonglong2 m23 = sm[i][1];
                a &= ~((1ull << k) | m23.x);
                alive3 &= ~m23.y;
            }
        }
        if (n < NSEL) {
            unsigned long long a = alive3;
            while (a && n < NSEL) {
                const int k = __ffsll((long long)a) - 1;
                const int i = 192 + k;
                sidx[n++] = i;
                a &= ~((1ull << k) | sm[i][1].y);
            }
        }
        for (int q2 = n; q2 < NSEL; ++q2) sidx[q2] = RR - NSEL + q2;  // fill = 192 + q
    }
    __syncthreads();

    // Clip the 64 selected ROIs, publish for the pooling kernel, emit tail output.
    if (t < NSEL) {
        const float4 rr = ((const float4*)roi)[b * RR + sidx[t]];
        int xmin = (int)fmaxf(0.0f, rr.x);
        int ymin = (int)fmaxf(0.0f, rr.y);
        int xmax = (int)fminf((float)WW, rr.x + rr.z);
        int ymax = (int)fminf((float)HH, rr.y + rr.w);
        fix_axis(xmin, xmax, PHW, WW);
        fix_axis(ymin, ymax, PHW, HH);
        int4 rc;
        rc.x = xmin; rc.y = ymin; rc.z = xmax - xmin; rc.w = ymax - ymin;
        g_roiclip[b * NSEL + t] = rc;
        sarea_i[t] = rc.z * rc.w;
        if (write_tail) {
            float* tp = out + (size_t)POOLED_ELEMS + (size_t)(b * NSEL + t) * 4;
            tp[0] = (float)rc.x; tp[1] = (float)rc.y;
            tp[2] = (float)rc.z; tp[3] = (float)rc.w;
        }
    }
    __syncthreads();

    // Rank by area desc. Batch-major order keeps concurrent CTAs within ~2 batches
    // so the feature working set stays L2-resident.
    if (t < NSEL) {
        const int a = sarea_i[t];
        int rank = 0;
#pragma unroll 8
        for (int j = 0; j < NSEL; ++j) {
            const int aj = sarea_i[j];
            rank += (aj > a) || (aj == a && j < t);
        }
        g_order[b * NSEL + rank] = b * NSEL + t;
    }
}

__device__ __forceinline__ float4 f4max(float4 a, float4 b) {
    return make_float4(fmaxf(a.x, b.x), fmaxf(a.y, b.y),
                       fmaxf(a.z, b.z), fmaxf(a.w, b.w));
}

// ---- Stage 2: pooling. grid = 4096 (ROI x channel-quarter), 8 groups x 32 float4-lanes ----
// R12-measured configuration (58.6us): plain launch_bounds(256), __stcs stores.
__global__ __launch_bounds__(256)
void pool_kernel(const float* __restrict__ feat, float* __restrict__ out) {
    const int slot = g_order[blockIdx.x >> 2];
    const int quarter = blockIdx.x & 3;
    const int b  = slot >> 6;
    const int4 rc = g_roiclip[slot];
    const int x = rc.x, y = rc.y, w = rc.z, h = rc.w;
    const int lane = threadIdx.x & 31;
    const int g    = threadIdx.x >> 5;           // group 0..7
    const int t    = quarter * 32 + lane;        // float4 lane in [0,128)
    const int CV   = CC / 4;                     // 128 float4 per position

    const float4* __restrict__ fm = (const float4*)feat + (size_t)b * HH * WW * CV;
    float4* __restrict__ o = (float4*)out + (size_t)slot * (PHW * PHW) * CV;

    const float NEGF = -__int_as_float(0x7f800000);
    const float4 NEG4 = make_float4(NEGF, NEGF, NEGF, NEGF);

    // ---- 6x6 direct copy: 36 positions; groups 0-7 take 4 each, groups 0-3 one extra ----
#pragma unroll
    for (int k = 0; k < 4; ++k) {
        const int p = g * 4 + k;
        const int i = p / 6, j = p - 6 * i;
        __stcs(&o[(i * 7 + j) * CV + t], fm[((y + i) * WW + (x + j)) * CV + t]);
    }
    if (g < 4) {
        const int p = 32 + g;
        const int i = p / 6, j = p - 6 * i;
        __stcs(&o[(i * 7 + j) * CV + t], fm[((y + i) * WW + (x + j)) * CV + t]);
    }

    // ---- strips: 12 tasks (0-5 col-strip rows, 6-11 row-strip cols) over 8 groups ----
#pragma unroll
    for (int rep = 0; rep < 2; ++rep) {
        const int s = rep == 0 ? g : (g < 4 ? 8 + g : 12);
        if (s < 6) {
            const int i = s;
            float4 a0 = NEG4, a1 = NEG4, a2 = NEG4, a3 = NEG4;
            const float4* row = fm + (size_t)(y + i) * WW * CV;
            int jj = x + 6;
            for (; jj + 3 < x + w; jj += 4) {
                a0 = f4max(a0, row[(jj    ) * CV + t]);
                a1 = f4max(a1, row[(jj + 1) * CV + t]);
                a2 = f4max(a2, row[(jj + 2) * CV + t]);
                a3 = f4max(a3, row[(jj + 3) * CV + t]);
            }
            for (; jj < x + w; ++jj) a0 = f4max(a0, row[jj * CV + t]);
            __stcs(&o[(i * 7 + 6) * CV + t], f4max(f4max(a0, a1), f4max(a2, a3)));
        } else if (s < 12) {
            const int j = s - 6;
            float4 a0 = NEG4, a1 = NEG4, a2 = NEG4, a3 = NEG4;
            const float4* col = fm + (size_t)(x + j) * CV;
            int ii = y + 6;
            for (; ii + 3 < y + h; ii += 4) {
                a0 = f4max(a0, col[(ii    ) * WW * CV + t]);
                a1 = f4max(a1, col[(ii + 1) * WW * CV + t]);
                a2 = f4max(a2, col[(ii + 2) * WW * CV + t]);
                a3 = f4max(a3, col[(ii + 3) * WW * CV + t]);
            }
            for (; ii < y + h; ++ii) a0 = f4max(a0, col[ii * WW * CV + t]);
            __stcs(&o[(42 + j) * CV + t], f4max(f4max(a0, a1), f4max(a2, a3)));
        }
    }

    // ---- corner: rows interleaved x8 across groups, smem combine ----
    {
        __shared__ float4 sbuf[7][32];
        float4 a0 = NEG4, a1 = NEG4, a2 = NEG4, a3 = NEG4;
        for (int ii = y + 6 + g; ii < y + h; ii += 8) {
            const float4* row = fm + (size_t)ii * WW * CV;
            int jj = x + 6;
            for (; jj + 3 < x + w; jj += 4) {
                a0 = f4max(a0, row[(jj    ) * CV + t]);
                a1 = f4max(a1, row[(jj + 1) * CV + t]);
                a2 = f4max(a2, row[(jj + 2) * CV + t]);
                a3 = f4max(a3, row[(jj + 3) * CV + t]);
            }
            for (; jj < x + w; ++jj) a0 = f4max(a0, row[jj * CV + t]);
        }
        float4 a = f4max(f4max(a0, a1), f4max(a2, a3));
        if (g > 0) sbuf[g - 1][lane] = a;
        __syncthreads();
        if (g == 0) {
            float4 m01 = f4max(sbuf[0][lane], sbuf[1][lane]);
            float4 m23 = f4max(sbuf[2][lane], sbuf[3][lane]);
            float4 m45 = f4max(sbuf[4][lane], sbuf[5][lane]);
            a = f4max(f4max(a, sbuf[6][lane]), f4max(f4max(m01, m23), m45));
            __stcs(&o[48 * CV + t], a);
        }
    }
}

extern "C" void kernel_launch(void* const* d_in, const int* in_sizes, int n_in,
                              void* d_out, int out_size) {
    const float* feat = (const float*)d_in[0];
    const float* roi  = (const float*)d_in[1];
    // defensive: identify inputs by size (features = 33,554,432; roi = 16,384)
    if (n_in >= 2 && in_sizes[0] == BB * RR * 4) {
        feat = (const float*)d_in[1];
        roi  = (const float*)d_in[0];
    }
    float* out = (float*)d_out;
    const int write_tail = (out_size >= POOLED_ELEMS + BB * NSEL * 4) ? 1 : 0;

    nms_kernel<<<dim3(BB, 16), RR>>>(roi, out, write_tail);
    pool_kernel<<<BB * NSEL * 4, 256>>>(feat, out);
}

// round 16
// speedup vs baseline: 1.1172x; 1.0256x over previous
#include <cuda_runtime.h>
#include <cstdint>

#define BB   16
#define HH   64
#define WW   64
#define CC   512
#define RR   256
#define NSEL 64
#define PHW  7
#define POOLED_ELEMS (BB * NSEL * PHW * PHW * CC)  // 25,690,112

__device__ int4 g_roiclip[BB * NSEL];
__device__ int  g_order[BB * NSEL];                    // batch-major, big-first within batch
__device__ unsigned long long g_mask[BB * RR * 4];     // upper-triangle suppression masks
__device__ int  g_cnt[BB];                             // zero-init; self-resetting per launch

__device__ __forceinline__ void fix_axis(int& mn, int& mx, int ps, int fs) {
    int pad = ps - (mx - mn);
    if (pad > 0) {
        if (mn < (pad >> 1))                { mn = 0;       mx = ps; }
        else if (fs - mx < ((1 + pad) >> 1)){ mn = fs - ps; mx = fs; }
        else { mn -= (pad >> 1); mx += (1 + pad) >> 1; }
    }
}

// ---- Stage 1 (fused): masks over 16-wide chunks (256 CTAs); the LAST CTA of each
//      batch resolves + clips + ranks ----
__global__ __launch_bounds__(RR)
void nms_kernel(const float* __restrict__ roi, float* __restrict__ out, int write_tail) {
    __shared__ float4 sbox[RR];   // x1, y1, x2, y2
    __shared__ float  sarea[RR];
    __shared__ int s_last;

    const int b = blockIdx.x;
    const int q = blockIdx.y;     // 16-wide j chunk, 0..15
    const int t = threadIdx.x;

    const float4 rv = ((const float4*)roi)[b * RR + t];
    const float x1 = rv.x, y1 = rv.y;
    const float x2 = rv.x + rv.z, y2 = rv.y + rv.w;
    const float area = (y2 - y1) * (x2 - x1);
    sbox[t]  = make_float4(x1, y1, x2, y2);
    sarea[t] = area;
    __syncthreads();

    unsigned mg = 0u;
    const int j0 = max(q * 16, t + 1);
    const int j1 = q * 16 + 16;
    for (int j = j0; j < j1; ++j) {
        const float4 o = sbox[j];
        const float ih = fmaxf(fminf(y2, o.w) - fmaxf(y1, o.y), 0.0f);
        const float iw = fmaxf(fminf(x2, o.z) - fmaxf(x1, o.x), 0.0f);
        const float inter = ih * iw;
        // inter == 0  =>  reference IoU is exactly 0 (no divide needed).
        // inter > 0   =>  union >= max(area) > 0, so the where() guard is satisfied.
        if (inter > 0.0f) {
            const float uni = area + sarea[j] - inter;
            // exact IEEE divide so the >0.4 decision matches JAX bit-for-bit
            const float iou = __fdiv_rn(inter, uni);
            if (iou > 0.4f) mg |= 1u << (j & 15);
        }
    }
    // u16 alias of the u64 mask array: word q covers bits [16q, 16q+16) (little-endian)
    ((unsigned short*)g_mask)[(b * RR + t) * 16 + q] = (unsigned short)mg;

    // Publish + count. Only the 16th (last) CTA of this batch continues to resolve.
    __threadfence();
    __syncthreads();
    if (t == 0) s_last = (atomicAdd(&g_cnt[b], 1) == 15) ? 1 : 0;
    __syncthreads();
    if (!s_last) return;
    __threadfence();                 // acquire: all 16 CTAs' mask writes now visible

    // ---- resolve phase (one CTA per batch) ----
    __shared__ ulonglong2 sm[RR][2];             // sm[i] = {w0,w1},{w2,w3}
    __shared__ int sidx[NSEL];
    __shared__ int sarea_i[NSEL];

    const ulonglong2* gm = (const ulonglong2*)(g_mask + (size_t)b * RR * 4);
    for (int idx = t; idx < RR * 2; idx += RR)
        ((ulonglong2*)sm)[idx] = gm[idx];
    __syncthreads();

    if (t == 0) {
        g_cnt[b] = 0;                // reset for the next graph replay
        int n = 0;
        unsigned long long alive1 = ~0ull, alive2 = ~0ull, alive3 = ~0ull;
        {
            unsigned long long a = ~0ull;
            while (a && n < NSEL) {
                const int k = __ffsll((long long)a) - 1;
                sidx[n++] = k;
                const ulonglong2 m01 = sm[k][0];
                const ulonglong2 m23 = sm[k][1];
                a &= ~((1ull << k) | m01.x);
                alive1 &= ~m01.y; alive2 &= ~m23.x; alive3 &= ~m23.y;
            }
        }
        if (n < NSEL) {
            unsigned long long a = alive1;
            while (a && n < NSEL) {
                const int k = __ffsll((long long)a) - 1;
                const int i = 64 + k;
                sidx[n++] = i;
                const ulonglong2 m01 = sm[i][0];
                const ulonglong2 m23 = sm[i][1];
                a &= ~((1ull << k) | m01.y);
                alive2 &= ~m23.x; alive3 &= ~m23.y;
            }
        }
        if (n < NSEL) {
            unsigned long long a = alive2;
            while (a && n < NSEL) {
                const int k = __ffsll((long long)a) - 1;
                const int i = 128 + k;
                sidx[n++] = i;
                const ulonglong2 m23 = sm[i][1];
                a &= ~((1ull << k) | m23.x);
                alive3 &= ~m23.y;
            }
        }
        if (n < NSEL) {
            unsigned long long a = alive3;
            while (a && n < NSEL) {
                const int k = __ffsll((long long)a) - 1;
                const int i = 192 + k;
                sidx[n++] = i;
                a &= ~((1ull << k) | sm[i][1].y);
            }
        }
        for (int q2 = n; q2 < NSEL; ++q2) sidx[q2] = RR - NSEL + q2;  // fill = 192 + q
    }
    __syncthreads();

    // Clip the 64 selected ROIs, publish for the pooling kernel, emit tail output.
    if (t < NSEL) {
        const float4 rr = ((const float4*)roi)[b * RR + sidx[t]];
        int xmin = (int)fmaxf(0.0f, rr.x);
        int ymin = (int)fmaxf(0.0f, rr.y);
        int xmax = (int)fminf((float)WW, rr.x + rr.z);
        int ymax = (int)fminf((float)HH, rr.y + rr.w);
        fix_axis(xmin, xmax, PHW, WW);
        fix_axis(ymin, ymax, PHW, HH);
        int4 rc;
        rc.x = xmin; rc.y = ymin; rc.z = xmax - xmin; rc.w = ymax - ymin;
        g_roiclip[b * NSEL + t] = rc;
        sarea_i[t] = rc.z * rc.w;
        if (write_tail) {
            float* tp = out + (size_t)POOLED_ELEMS + (size_t)(b * NSEL + t) * 4;
            tp[0] = (float)rc.x; tp[1] = (float)rc.y;
            tp[2] = (float)rc.z; tp[3] = (float)rc.w;
        }
    }
    __syncthreads();

    // Rank by area desc. Batch-major order keeps concurrent CTAs within ~2 batches
    // so the feature working set stays L2-resident.
    if (t < NSEL) {
        const int a = sarea_i[t];
        int rank = 0;
#pragma unroll 8
        for (int j = 0; j < NSEL; ++j) {
            const int aj = sarea_i[j];
            rank += (aj > a) || (aj == a && j < t);
        }
        g_order[b * NSEL + rank] = b * NSEL + t;
    }
}

__device__ __forceinline__ float4 f4max(float4 a, float4 b) {
    return make_float4(fmaxf(a.x, b.x), fmaxf(a.y, b.y),
                       fmaxf(a.z, b.z), fmaxf(a.w, b.w));
}

// ---- Stage 2: pooling. grid = 8192 (ROI x channel-eighth), 128 threads =
//      8 groups x 16 float4-lanes. Same task split/chains as the 256-thr version;
//      finer CTA granularity -> 16 resident CTAs/SM, better packing of
//      variable-duration CTAs. ----
__global__ __launch_bounds__(128)
void pool_kernel(const float* __restrict__ feat, float* __restrict__ out) {
    const int slot  = g_order[blockIdx.x >> 3];
    const int chunk = blockIdx.x & 7;
    const int b  = slot >> 6;
    const int4 rc = g_roiclip[slot];
    const int x = rc.x, y = rc.y, w = rc.z, h = rc.w;
    const int lane = threadIdx.x & 15;
    const int g    = threadIdx.x >> 4;           // group 0..7
    const int t    = chunk * 16 + lane;          // float4 lane in [0,128)
    const int CV   = CC / 4;                     // 128 float4 per position

    const float4* __restrict__ fm = (const float4*)feat + (size_t)b * HH * WW * CV;
    float4* __restrict__ o = (float4*)out + (size_t)slot * (PHW * PHW) * CV;

    const float NEGF = -__int_as_float(0x7f800000);
    const float4 NEG4 = make_float4(NEGF, NEGF, NEGF, NEGF);

    // ---- 6x6 direct copy: 36 positions; groups 0-7 take 4 each, groups 0-3 one extra ----
#pragma unroll
    for (int k = 0; k < 4; ++k) {
        const int p = g * 4 + k;
        const int i = p / 6, j = p - 6 * i;
        __stcs(&o[(i * 7 + j) * CV + t], fm[((y + i) * WW + (x + j)) * CV + t]);
    }
    if (g < 4) {
        const int p = 32 + g;
        const int i = p / 6, j = p - 6 * i;
        __stcs(&o[(i * 7 + j) * CV + t], fm[((y + i) * WW + (x + j)) * CV + t]);
    }

    // ---- strips: 12 tasks (0-5 col-strip rows, 6-11 row-strip cols) over 8 groups ----
#pragma unroll
    for (int rep = 0; rep < 2; ++rep) {
        const int s = rep == 0 ? g : (g < 4 ? 8 + g : 12);
        if (s < 6) {
            const int i = s;
            float4 a0 = NEG4, a1 = NEG4, a2 = NEG4, a3 = NEG4;
            const float4* row = fm + (size_t)(y + i) * WW * CV;
            int jj = x + 6;
            for (; jj + 3 < x + w; jj += 4) {
                a0 = f4max(a0, row[(jj    ) * CV + t]);
                a1 = f4max(a1, row[(jj + 1) * CV + t]);
                a2 = f4max(a2, row[(jj + 2) * CV + t]);
                a3 = f4max(a3, row[(jj + 3) * CV + t]);
            }
            for (; jj < x + w; ++jj) a0 = f4max(a0, row[jj * CV + t]);
            __stcs(&o[(i * 7 + 6) * CV + t], f4max(f4max(a0, a1), f4max(a2, a3)));
        } else if (s < 12) {
            const int j = s - 6;
            float4 a0 = NEG4, a1 = NEG4, a2 = NEG4, a3 = NEG4;
            const float4* col = fm + (size_t)(x + j) * CV;
            int ii = y + 6;
            for (; ii + 3 < y + h; ii += 4) {
                a0 = f4max(a0, col[(ii    ) * WW * CV + t]);
                a1 = f4max(a1, col[(ii + 1) * WW * CV + t]);
                a2 = f4max(a2, col[(ii + 2) * WW * CV + t]);
                a3 = f4max(a3, col[(ii + 3) * WW * CV + t]);
            }
            for (; ii < y + h; ++ii) a0 = f4max(a0, col[ii * WW * CV + t]);
            __stcs(&o[(42 + j) * CV + t], f4max(f4max(a0, a1), f4max(a2, a3)));
        }
    }

    // ---- corner: rows interleaved x8 across groups, smem combine ----
    {
        __shared__ float4 sbuf[7][16];
        float4 a0 = NEG4, a1 = NEG4, a2 = NEG4, a3 = NEG4;
        for (int ii = y + 6 + g; ii < y + h; ii += 8) {
            const float4* row = fm + (size_t)ii * WW * CV;
            int jj = x + 6;
            for (; jj + 3 < x + w; jj += 4) {
                a0 = f4max(a0, row[(jj    ) * CV + t]);
                a1 = f4max(a1, row[(jj + 1) * CV + t]);
                a2 = f4max(a2, row[(jj + 2) * CV + t]);
                a3 = f4max(a3, row[(jj + 3) * CV + t]);
            }
            for (; jj < x + w; ++jj) a0 = f4max(a0, row[jj * CV + t]);
        }
        float4 a = f4max(f4max(a0, a1), f4max(a2, a3));
        if (g > 0) sbuf[g - 1][lane] = a;
        __syncthreads();
        if (g == 0) {
            float4 m01 = f4max(sbuf[0][lane], sbuf[1][lane]);
            float4 m23 = f4max(sbuf[2][lane], sbuf[3][lane]);
            float4 m45 = f4max(sbuf[4][lane], sbuf[5][lane]);
            a = f4max(f4max(a, sbuf[6][lane]), f4max(f4max(m01, m23), m45));
            __stcs(&o[48 * CV + t], a);
        }
    }
}

extern "C" void kernel_launch(void* const* d_in, const int* in_sizes, int n_in,
                              void* d_out, int out_size) {
    const float* feat = (const float*)d_in[0];
    const float* roi  = (const float*)d_in[1];
    // defensive: identify inputs by size (features = 33,554,432; roi = 16,384)
    if (n_in >= 2 && in_sizes[0] == BB * RR * 4) {
        feat = (const float*)d_in[1];
        roi  = (const float*)d_in[0];
    }
    float* out = (float*)d_out;
    const int write_tail = (out_size >= POOLED_ELEMS + BB * NSEL * 4) ? 1 : 0;

    nms_kernel<<<dim3(BB, 16), RR>>>(roi, out, write_tail);
    pool_kernel<<<BB * NSEL * 8, 128>>>(feat, out);
}